// round 15
// baseline (speedup 1.0000x reference)
#include <cuda_runtime.h>

typedef unsigned long long u64;

#define NK 16
#define KT 11            // kernels 0..KT-1: tanh tail; KT..15: ex2+magic-Newton tail
#define TW 136           // tile row stride in floats

struct CB {
    u64 crec[NK][12];    // per-k: [w0..w8 (dup), mk (dup), pk (dup), pad]
    float psumh;         // 0.5 * sum_{k<KT}(products)
    float pad;
};

__constant__ CB c_cb;    // backing store written directly by setup_kernel

__device__ __forceinline__ u64 pack2(float lo, float hi) {
    u64 r; asm("mov.b64 %0, {%1, %2};" : "=l"(r) : "f"(lo), "f"(hi)); return r;
}
__device__ __forceinline__ void unpack2(u64 v, float& lo, float& hi) {
    asm("mov.b64 {%0, %1}, %2;" : "=f"(lo), "=f"(hi) : "l"(v));
}
__device__ __forceinline__ u64 fma2(u64 a, u64 b, u64 c) {
    u64 d; asm("fma.rn.f32x2 %0, %1, %2, %3;" : "=l"(d) : "l"(a), "l"(b), "l"(c)); return d;
}
__device__ __forceinline__ u64 add2_(u64 a, u64 b) {
    u64 d; asm("add.rn.f32x2 %0, %1, %2;" : "=l"(d) : "l"(a), "l"(b)); return d;
}
__device__ __forceinline__ void tanh2_ip(u64& v) {
    asm("{\n\t"
        ".reg .f32 lo, hi;\n\t"
        "mov.b64 {lo, hi}, %0;\n\t"
        "tanh.approx.f32 lo, lo;\n\t"
        "tanh.approx.f32 hi, hi;\n\t"
        "mov.b64 %0, {lo, hi};\n\t"
        "}" : "+l"(v));
}
__device__ __forceinline__ float addsat_(float a, float b) {
    float r; asm("add.rn.sat.f32 %0, %1, %2;" : "=f"(r) : "f"(a), "f"(b)); return r;
}
__device__ __forceinline__ float ex2_(float a) {
    float r; asm("ex2.approx.f32 %0, %1;" : "=f"(r) : "f"(a)); return r;
}
// sigma = 1/(1+2^w), scalar, no MUFU rcp: ex2 + magic-constant reciprocal
// with 2 Newton steps (alu IADD + 4 fma-pipe scalar ops). All-scalar: no
// register-pair alignment pressure.
__device__ __forceinline__ float sig_ex2(float w) {
    float t = ex2_(fminf(w, 60.0f));                  // t = 2^w, clamped
    float u = t + 1.0f;
    float y = __int_as_float(0x7EF311C3 - __float_as_int(u));  // ~5% recip guess
    y = y * (2.0f - u * y);                           // Newton 1
    y = y * (2.0f - u * y);                           // Newton 2 (~7e-6 rel)
    return y;
}

#define C2 (-14.4269504088896341f)   // -10*log2(e)

// Setup: write transformed constants DIRECTLY into c_cb's backing store.
// k<KT: z-domain (5w, -5r, 0.5p) for tanh tail.
// k>=KT: w-domain (C2*w, -C2*r, p) for ex2 tail.
__global__ void setup_kernel(CB* __restrict__ dst,
                             const float* __restrict__ w,
                             const float* __restrict__ react,
                             const float* __restrict__ prod)
{
    int tid = threadIdx.x;
    if (tid < NK * 12) {
        int k = tid / 12, j = tid - k * 12;
        float sc = (k < KT) ? 5.0f : C2;
        u64 v = 0ull;
        if (j < 9) {
            float t = sc * w[k * 9 + j];
            v = pack2(t, t);
        } else if (j == 9) {
            float t = -sc * react[k];
            v = pack2(t, t);
        } else if (j == 10) {
            float t = (k < KT) ? 0.5f * prod[k] : prod[k];
            v = pack2(t, t);
        }
        dst->crec[k][j] = v;
    } else if (tid == NK * 12) {
        float s = 0.0f;
        #pragma unroll
        for (int k = 0; k < KT; k++) s += prod[k];
        dst->psumh = 0.5f * s;
        dst->pad = 0.0f;
    }
}

// Grid: (4 col-tiles, 64 row-tiles, 16 batch). Block (64,4) = 256 thr.
// Thread: 2 rows x 2 cols = 4 px (2 vertical-row pairs per column... row pairs).
__global__ void __launch_bounds__(256, 3)
ca_kernel(const float* __restrict__ x, float* __restrict__ out)
{
    __shared__ __align__(16) float tile[10][TW];   // rows gy0-1 .. gy0+8

    const int bx  = blockIdx.x;
    const int by  = blockIdx.y;
    const int b   = blockIdx.z;
    const int tx  = threadIdx.x;
    const int ty  = threadIdx.y;
    const int tid = ty * 64 + tx;

    // ---- tile load: 10 rows x 34 float4 ----
    const float* xb = x + (size_t)b * (512 * 512);
    #pragma unroll
    for (int it = 0; it < 2; it++) {
        int i = tid + it * 256;
        if (i < 340) {
            int r   = i / 34;
            int c4  = i - r * 34;
            int gy  = by * 8 + r - 1;
            int gc0 = bx * 128 + c4 * 4 - 4;
            float4 v = make_float4(0.f, 0.f, 0.f, 0.f);
            if ((unsigned)gy < 512u && (unsigned)gc0 < 512u)
                v = *(const float4*)(xb + (size_t)gy * 512 + gc0);
            *(float4*)&tile[r][c4 * 4] = v;
        }
    }
    __syncthreads();

    // ---- register neighborhood: 4 tile rows x 3 windows ----
    u64 nb[4][3];
    #pragma unroll
    for (int q = 0; q < 4; q++) {
        const float* trow = tile[2 * ty + q];
        u64 L = *(const u64*)(trow + 2 * tx + 2);
        u64 M = *(const u64*)(trow + 2 * tx + 4);
        u64 R = *(const u64*)(trow + 2 * tx + 6);
        float l0, l1, m0, m1, r0, r1;
        unpack2(L, l0, l1);
        unpack2(M, m0, m1);
        unpack2(R, r0, r1);
        nb[q][0] = pack2(l1, m0);
        nb[q][1] = M;
        nb[q][2] = pack2(m1, r0);
    }

    const u64 TWO2 = pack2(2.0f, 2.0f);

    u64 aP0 = 0ull, aP1 = 0ull;   // k<KT: sum(t_k*0.5p_k); k>=KT: sum(sigma_k*p_k)
    u64 aS0 = 0ull, aS1 = 0ull;   // k<KT: sum(t_k);        k>=KT: sum(2*sigma_k)

    #pragma unroll
    for (int k = 0; k < NK; k++) {
        const u64* cr = c_cb.crec[k];
        const u64 mk  = cr[9];
        const u64 pkk = cr[10];

        // conv chains (z-domain for k<KT, w-domain for k>=KT; same shape)
        u64 z0 = fma2(cr[0], nb[0][0], mk);
        u64 z1 = fma2(cr[0], nb[1][0], mk);
        z0 = fma2(cr[1], nb[0][1], z0);  z1 = fma2(cr[1], nb[1][1], z1);
        z0 = fma2(cr[2], nb[0][2], z0);  z1 = fma2(cr[2], nb[1][2], z1);
        z0 = fma2(cr[3], nb[1][0], z0);  z1 = fma2(cr[3], nb[2][0], z1);
        z0 = fma2(cr[4], nb[1][1], z0);  z1 = fma2(cr[4], nb[2][1], z1);
        z0 = fma2(cr[5], nb[1][2], z0);  z1 = fma2(cr[5], nb[2][2], z1);
        z0 = fma2(cr[6], nb[2][0], z0);  z1 = fma2(cr[6], nb[3][0], z1);
        z0 = fma2(cr[7], nb[2][1], z0);  z1 = fma2(cr[7], nb[3][1], z1);
        z0 = fma2(cr[8], nb[2][2], z0);  z1 = fma2(cr[8], nb[3][2], z1);

        if (k < KT) {
            // tanh tail (proven: MUFU rt16, alu-light)
            tanh2_ip(z0);
            tanh2_ip(z1);
            aP0 = fma2(z0, pkk, aP0);  aS0 = add2_(z0, aS0);
            aP1 = fma2(z1, pkk, aP1);  aS1 = add2_(z1, aS1);
        } else {
            // ex2 + magic-Newton tail (MUFU rt8; extra work on fma/alu pipes,
            // all-scalar to avoid pair-alignment MOVs)
            float w0, w1, w2, w3;
            unpack2(z0, w0, w1);
            unpack2(z1, w2, w3);
            u64 s0 = pack2(sig_ex2(w0), sig_ex2(w1));
            u64 s1 = pack2(sig_ex2(w2), sig_ex2(w3));
            aP0 = fma2(s0, pkk, aP0);  aS0 = fma2(s0, TWO2, aS0);
            aP1 = fma2(s1, pkk, aP1);  aS1 = fma2(s1, TWO2, aS1);
        }
    }

    // ---- epilogue ----
    // sum(sigma) over all k = (KT/2) + 0.5*aS  (both tail kinds normalized via aS)
    // out = sat( psumh + aP + x*(1 - KT/2 - 0.5*aS) ), 1 - 5.5 = -4.5
    const float ps = c_cb.psumh;
    const u64 MH2 = pack2(-0.5f, -0.5f);
    const u64 MC2 = pack2(-4.5f, -4.5f);

    u64 o0 = fma2(nb[1][1], fma2(aS0, MH2, MC2), aP0);   // centers row 0
    u64 o1 = fma2(nb[2][1], fma2(aS1, MH2, MC2), aP1);   // centers row 1
    float a0, a1, b0, b1;
    unpack2(o0, a0, a1);
    unpack2(o1, b0, b1);

    const int gy0 = by * 8 + 2 * ty;
    float* ob = out + (size_t)b * (512 * 512) + (size_t)gy0 * 512 + bx * 128 + 2 * tx;
    *(float2*)ob         = make_float2(addsat_(a0, ps), addsat_(a1, ps));
    *(float2*)(ob + 512) = make_float2(addsat_(b0, ps), addsat_(b1, ps));
}

extern "C" void kernel_launch(void* const* d_in, const int* in_sizes, int n_in,
                              void* d_out, int out_size) {
    const float* x = (const float*)d_in[0];
    const float* w = (const float*)d_in[1];
    const float* r = (const float*)d_in[2];
    const float* p = (const float*)d_in[3];

    void* csym = nullptr;
    cudaGetSymbolAddress(&csym, c_cb);

    setup_kernel<<<1, 256>>>((CB*)csym, w, r, p);

    dim3 grid(4, 64, 16);
    dim3 block(64, 4);
    ca_kernel<<<grid, block>>>(x, (float*)d_out);
}

// round 16
// speedup vs baseline: 1.0589x; 1.0589x over previous
#include <cuda_runtime.h>

typedef unsigned long long u64;

#define NK 16
#define TW 136           // tile row stride in floats

struct CB {
    u64 crec[NK][12];    // [w0..w8 (x5, dup), mk=(-5r,dup), pk=(0.5p,dup), pad]
    float psumh;         // 0.5 * sum(products)
    float pad;
};

__constant__ CB c_cb;    // backing store written directly by setup_kernel

__device__ __forceinline__ u64 pack2(float lo, float hi) {
    u64 r; asm("mov.b64 %0, {%1, %2};" : "=l"(r) : "f"(lo), "f"(hi)); return r;
}
__device__ __forceinline__ void unpack2(u64 v, float& lo, float& hi) {
    asm("mov.b64 {%0, %1}, %2;" : "=f"(lo), "=f"(hi) : "l"(v));
}
__device__ __forceinline__ u64 fma2(u64 a, u64 b, u64 c) {
    u64 d; asm("fma.rn.f32x2 %0, %1, %2, %3;" : "=l"(d) : "l"(a), "l"(b), "l"(c)); return d;
}
__device__ __forceinline__ u64 add2_(u64 a, u64 b) {
    u64 d; asm("add.rn.f32x2 %0, %1, %2;" : "=l"(d) : "l"(a), "l"(b)); return d;
}
// tanh on both halves via ONE MUFU f16x2 op: fp32 pair -> f16x2 -> tanh -> fp32
// pair, in place. Halves the MUFU instruction count vs 2x scalar tanh; the two
// cvts ride the alu/xu pipes which have slack.
__device__ __forceinline__ void tanh2_h2_ip(u64& v) {
    asm("{\n\t"
        ".reg .f32 lo, hi;\n\t"
        ".reg .b32 h;\n\t"
        ".reg .f16 pl, ph;\n\t"
        "mov.b64 {lo, hi}, %0;\n\t"
        "cvt.rn.f16x2.f32 h, hi, lo;\n\t"      // h = {lo(lo16), hi(hi16)}
        "tanh.approx.f16x2 h, h;\n\t"           // one MUFU op, two tanh
        "mov.b32 {pl, ph}, h;\n\t"
        "cvt.f32.f16 lo, pl;\n\t"
        "cvt.f32.f16 hi, ph;\n\t"
        "mov.b64 %0, {lo, hi};\n\t"
        "}" : "+l"(v));
}
__device__ __forceinline__ float addsat_(float a, float b) {
    float r; asm("add.rn.sat.f32 %0, %1, %2;" : "=f"(r) : "f"(a), "f"(b)); return r;
}

// Setup: write transformed constants DIRECTLY into c_cb's backing store.
__global__ void setup_kernel(CB* __restrict__ dst,
                             const float* __restrict__ w,
                             const float* __restrict__ react,
                             const float* __restrict__ prod)
{
    int tid = threadIdx.x;
    if (tid < NK * 12) {
        int k = tid / 12, j = tid - k * 12;
        u64 v = 0ull;
        if (j < 9) {
            float t = 5.0f * w[k * 9 + j];       // fold GAIN/2 into weights
            v = pack2(t, t);
        } else if (j == 9) {
            float t = -5.0f * react[k];          // z = 5N - 5r
            v = pack2(t, t);
        } else if (j == 10) {
            float t = 0.5f * prod[k];
            v = pack2(t, t);
        }
        dst->crec[k][j] = v;
    } else if (tid == NK * 12) {
        float s = 0.0f;
        #pragma unroll
        for (int k = 0; k < NK; k++) s += prod[k];
        dst->psumh = 0.5f * s;
        dst->pad = 0.0f;
    }
}

// Grid: (4 col-tiles, 64 row-tiles, 16 batch). Block (64,4) = 256 thr.
// Block covers 8 rows x 128 cols. Thread: 2 rows x 2 cols = 4 px (2 pairs).
__global__ void __launch_bounds__(256, 4)
ca_kernel(const float* __restrict__ x, float* __restrict__ out)
{
    __shared__ __align__(16) float tile[10][TW];   // rows gy0-1 .. gy0+8

    const int bx  = blockIdx.x;
    const int by  = blockIdx.y;
    const int b   = blockIdx.z;
    const int tx  = threadIdx.x;            // 0..63 -> col pair 2*tx
    const int ty  = threadIdx.y;            // 0..3  -> rows 2*ty, 2*ty+1
    const int tid = ty * 64 + tx;

    // ---- tile load: 10 rows x 34 float4 = 340 loads ----
    const float* xb = x + (size_t)b * (512 * 512);
    #pragma unroll
    for (int it = 0; it < 2; it++) {
        int i = tid + it * 256;
        if (i < 340) {
            int r   = i / 34;
            int c4  = i - r * 34;
            int gy  = by * 8 + r - 1;
            int gc0 = bx * 128 + c4 * 4 - 4;
            float4 v = make_float4(0.f, 0.f, 0.f, 0.f);
            if ((unsigned)gy < 512u && (unsigned)gc0 < 512u)
                v = *(const float4*)(xb + (size_t)gy * 512 + gc0);
            *(float4*)&tile[r][c4 * 4] = v;
        }
    }
    __syncthreads();

    // ---- register neighborhood: 4 tile rows x 3 windows (all LDS.64-aligned) ----
    u64 nb[4][3];
    #pragma unroll
    for (int q = 0; q < 4; q++) {
        const float* trow = tile[2 * ty + q];
        u64 L = *(const u64*)(trow + 2 * tx + 2);
        u64 M = *(const u64*)(trow + 2 * tx + 4);
        u64 R = *(const u64*)(trow + 2 * tx + 6);
        float l0, l1, m0, m1, r0, r1;
        unpack2(L, l0, l1);
        unpack2(M, m0, m1);
        unpack2(R, r0, r1);
        nb[q][0] = pack2(l1, m0);   // (v0, v1)
        nb[q][1] = M;               // (v1, v2)
        nb[q][2] = pack2(m1, r0);   // (v2, v3)
    }

    u64 aP0 = 0ull, aP1 = 0ull;   // sum(t_k * 0.5 p_k), rows 0/1
    u64 aS0 = 0ull, aS1 = 0ull;   // sum(t_k)

    #pragma unroll
    for (int k = 0; k < NK; k++) {
        const u64* cr = c_cb.crec[k];    // uniform const loads (ULDC)
        const u64 mk  = cr[9];
        const u64 pkk = cr[10];

        // conv chains init with bias -> z = 5N - 5r directly
        u64 z0 = fma2(cr[0], nb[0][0], mk);     // row 0 (tile rows 0..2)
        u64 z1 = fma2(cr[0], nb[1][0], mk);     // row 1 (tile rows 1..3)
        z0 = fma2(cr[1], nb[0][1], z0);  z1 = fma2(cr[1], nb[1][1], z1);
        z0 = fma2(cr[2], nb[0][2], z0);  z1 = fma2(cr[2], nb[1][2], z1);
        z0 = fma2(cr[3], nb[1][0], z0);  z1 = fma2(cr[3], nb[2][0], z1);
        z0 = fma2(cr[4], nb[1][1], z0);  z1 = fma2(cr[4], nb[2][1], z1);
        z0 = fma2(cr[5], nb[1][2], z0);  z1 = fma2(cr[5], nb[2][2], z1);
        z0 = fma2(cr[6], nb[2][0], z0);  z1 = fma2(cr[6], nb[3][0], z1);
        z0 = fma2(cr[7], nb[2][1], z0);  z1 = fma2(cr[7], nb[3][1], z1);
        z0 = fma2(cr[8], nb[2][2], z0);  z1 = fma2(cr[8], nb[3][2], z1);

        tanh2_h2_ip(z0);     // one f16x2 MUFU op per pair (was two scalar tanh)
        tanh2_h2_ip(z1);

        aP0 = fma2(z0, pkk, aP0);  aS0 = add2_(z0, aS0);
        aP1 = fma2(z1, pkk, aP1);  aS1 = add2_(z1, aS1);
    }

    // ---- epilogue: out = sat( 0.5*sum(p) + aP + x*(-0.5*aS - 7) ) ----
    const float ps = c_cb.psumh;
    const u64 MH2 = pack2(-0.5f, -0.5f);
    const u64 M72 = pack2(-7.0f, -7.0f);

    u64 o0 = fma2(nb[1][1], fma2(aS0, MH2, M72), aP0);   // centers row 0
    u64 o1 = fma2(nb[2][1], fma2(aS1, MH2, M72), aP1);   // centers row 1
    float a0, a1, b0, b1;
    unpack2(o0, a0, a1);
    unpack2(o1, b0, b1);

    const int gy0 = by * 8 + 2 * ty;
    float* ob = out + (size_t)b * (512 * 512) + (size_t)gy0 * 512 + bx * 128 + 2 * tx;
    *(float2*)ob         = make_float2(addsat_(a0, ps), addsat_(a1, ps));
    *(float2*)(ob + 512) = make_float2(addsat_(b0, ps), addsat_(b1, ps));
}

extern "C" void kernel_launch(void* const* d_in, const int* in_sizes, int n_in,
                              void* d_out, int out_size) {
    const float* x = (const float*)d_in[0];
    const float* w = (const float*)d_in[1];
    const float* r = (const float*)d_in[2];
    const float* p = (const float*)d_in[3];

    void* csym = nullptr;
    cudaGetSymbolAddress(&csym, c_cb);

    setup_kernel<<<1, 256>>>((CB*)csym, w, r, p);

    dim3 grid(4, 64, 16);   // 4 col-tiles x 64 row-tiles x 16 batch
    dim3 block(64, 4);
    ca_kernel<<<grid, block>>>(x, (float*)d_out);
}

// round 17
// speedup vs baseline: 1.1242x; 1.0616x over previous
#include <cuda_runtime.h>

typedef unsigned long long u64;

#define NK 16
#define TW 136           // tile row stride in floats (col c stores gcol = bx*128 + c - 4)

struct CB {
    u64 crec[NK][12];    // [w0..w8 (x5, dup), mk=(-5r,dup), pk=(0.5p,dup), pad]
    float psumh;         // 0.5 * sum(products)
    float pad;
};

__device__   CB g_cb;    // written by setup kernel
__constant__ CB c_cb;    // main kernel reads (uniform const port, off the smem crossbar)

__device__ __forceinline__ u64 pack2(float lo, float hi) {
    u64 r; asm("mov.b64 %0, {%1, %2};" : "=l"(r) : "f"(lo), "f"(hi)); return r;
}
__device__ __forceinline__ void unpack2(u64 v, float& lo, float& hi) {
    asm("mov.b64 {%0, %1}, %2;" : "=f"(lo), "=f"(hi) : "l"(v));
}
__device__ __forceinline__ u64 fma2(u64 a, u64 b, u64 c) {
    u64 d; asm("fma.rn.f32x2 %0, %1, %2, %3;" : "=l"(d) : "l"(a), "l"(b), "l"(c)); return d;
}
__device__ __forceinline__ u64 add2_(u64 a, u64 b) {
    u64 d; asm("add.rn.f32x2 %0, %1, %2;" : "=l"(d) : "l"(a), "l"(b)); return d;
}
__device__ __forceinline__ void tanh2_ip(u64& v) {
    asm("{\n\t"
        ".reg .f32 lo, hi;\n\t"
        "mov.b64 {lo, hi}, %0;\n\t"
        "tanh.approx.f32 lo, lo;\n\t"
        "tanh.approx.f32 hi, hi;\n\t"
        "mov.b64 %0, {lo, hi};\n\t"
        "}" : "+l"(v));
}
__device__ __forceinline__ float addsat_(float a, float b) {
    float r; asm("add.rn.sat.f32 %0, %1, %2;" : "=f"(r) : "f"(a), "f"(b)); return r;
}

// Setup: transform raw params into the packed constant record (1 block, 256 thr).
__global__ void setup_kernel(const float* __restrict__ w,
                             const float* __restrict__ react,
                             const float* __restrict__ prod)
{
    int tid = threadIdx.x;
    if (tid < NK * 12) {
        int k = tid / 12, j = tid - k * 12;
        u64 v = 0ull;
        if (j < 9) {
            float t = 5.0f * w[k * 9 + j];       // fold GAIN/2 into weights
            v = pack2(t, t);
        } else if (j == 9) {
            float t = -5.0f * react[k];          // z = 5N - 5r
            v = pack2(t, t);
        } else if (j == 10) {
            float t = 0.5f * prod[k];
            v = pack2(t, t);
        }
        g_cb.crec[k][j] = v;
    } else if (tid == NK * 12) {
        float s = 0.0f;
        #pragma unroll
        for (int k = 0; k < NK; k++) s += prod[k];
        g_cb.psumh = 0.5f * s;
        g_cb.pad = 0.0f;
    }
}

// Grid: (4 col-tiles, 64 row-tiles, 16 batch). Block (64,4) = 256 thr.
// Block covers 8 rows x 128 cols. Thread: 2 rows x 2 cols = 4 px (2 pairs).
__global__ void __launch_bounds__(256, 4)
ca_kernel(const float* __restrict__ x, float* __restrict__ out)
{
    __shared__ __align__(16) float tile[10][TW];   // rows gy0-1 .. gy0+8

    const int bx  = blockIdx.x;
    const int by  = blockIdx.y;
    const int b   = blockIdx.z;
    const int tx  = threadIdx.x;            // 0..63 -> col pair 2*tx
    const int ty  = threadIdx.y;            // 0..3  -> rows 2*ty, 2*ty+1
    const int tid = ty * 64 + tx;

    // ---- tile load: 10 rows x 34 float4 = 340 loads ----
    // tile[r][c] stores gcol = bx*128 + c - 4, row gy = by*8 + r - 1.
    const float* xb = x + (size_t)b * (512 * 512);
    #pragma unroll
    for (int it = 0; it < 2; it++) {
        int i = tid + it * 256;
        if (i < 340) {
            int r   = i / 34;
            int c4  = i - r * 34;
            int gy  = by * 8 + r - 1;
            int gc0 = bx * 128 + c4 * 4 - 4;
            float4 v = make_float4(0.f, 0.f, 0.f, 0.f);
            if ((unsigned)gy < 512u && (unsigned)gc0 < 512u)
                v = *(const float4*)(xb + (size_t)gy * 512 + gc0);
            *(float4*)&tile[r][c4 * 4] = v;
        }
    }
    __syncthreads();

    // ---- register neighborhood: 4 tile rows x 3 windows (all LDS.64-aligned) ----
    u64 nb[4][3];
    #pragma unroll
    for (int q = 0; q < 4; q++) {
        const float* trow = tile[2 * ty + q];
        u64 L = *(const u64*)(trow + 2 * tx + 2);
        u64 M = *(const u64*)(trow + 2 * tx + 4);
        u64 R = *(const u64*)(trow + 2 * tx + 6);
        float l0, l1, m0, m1, r0, r1;
        unpack2(L, l0, l1);
        unpack2(M, m0, m1);
        unpack2(R, r0, r1);
        nb[q][0] = pack2(l1, m0);   // (v0, v1)
        nb[q][1] = M;               // (v1, v2)
        nb[q][2] = pack2(m1, r0);   // (v2, v3)
    }

    u64 aP0 = 0ull, aP1 = 0ull;   // sum(t_k * 0.5 p_k), rows 0/1
    u64 aS0 = 0ull, aS1 = 0ull;   // sum(t_k)

    #pragma unroll
    for (int k = 0; k < NK; k++) {
        const u64* cr = c_cb.crec[k];    // uniform const loads (ULDC), no smem traffic
        const u64 mk  = cr[9];
        const u64 pkk = cr[10];

        // conv chains init with bias -> z = 5N - 5r directly
        u64 z0 = fma2(cr[0], nb[0][0], mk);     // row 0 (tile rows 0..2)
        u64 z1 = fma2(cr[0], nb[1][0], mk);     // row 1 (tile rows 1..3)
        z0 = fma2(cr[1], nb[0][1], z0);  z1 = fma2(cr[1], nb[1][1], z1);
        z0 = fma2(cr[2], nb[0][2], z0);  z1 = fma2(cr[2], nb[1][2], z1);
        z0 = fma2(cr[3], nb[1][0], z0);  z1 = fma2(cr[3], nb[2][0], z1);
        z0 = fma2(cr[4], nb[1][1], z0);  z1 = fma2(cr[4], nb[2][1], z1);
        z0 = fma2(cr[5], nb[1][2], z0);  z1 = fma2(cr[5], nb[2][2], z1);
        z0 = fma2(cr[6], nb[2][0], z0);  z1 = fma2(cr[6], nb[3][0], z1);
        z0 = fma2(cr[7], nb[2][1], z0);  z1 = fma2(cr[7], nb[3][1], z1);
        z0 = fma2(cr[8], nb[2][2], z0);  z1 = fma2(cr[8], nb[3][2], z1);

        tanh2_ip(z0);
        tanh2_ip(z1);

        aP0 = fma2(z0, pkk, aP0);  aS0 = add2_(z0, aS0);
        aP1 = fma2(z1, pkk, aP1);  aS1 = add2_(z1, aS1);
    }

    // ---- epilogue: out = sat( 0.5*sum(p) + aP + x*(-0.5*aS - 7) ) ----
    const float ps = c_cb.psumh;
    const u64 MH2 = pack2(-0.5f, -0.5f);
    const u64 M72 = pack2(-7.0f, -7.0f);

    u64 o0 = fma2(nb[1][1], fma2(aS0, MH2, M72), aP0);   // centers row 0
    u64 o1 = fma2(nb[2][1], fma2(aS1, MH2, M72), aP1);   // centers row 1
    float a0, a1, b0, b1;
    unpack2(o0, a0, a1);
    unpack2(o1, b0, b1);

    const int gy0 = by * 8 + 2 * ty;
    float* ob = out + (size_t)b * (512 * 512) + (size_t)gy0 * 512 + bx * 128 + 2 * tx;
    *(float2*)ob         = make_float2(addsat_(a0, ps), addsat_(a1, ps));
    *(float2*)(ob + 512) = make_float2(addsat_(b0, ps), addsat_(b1, ps));
}

extern "C" void kernel_launch(void* const* d_in, const int* in_sizes, int n_in,
                              void* d_out, int out_size) {
    const float* x = (const float*)d_in[0];
    const float* w = (const float*)d_in[1];
    const float* r = (const float*)d_in[2];
    const float* p = (const float*)d_in[3];

    // 1) compute transformed constants into g_cb (device global)
    setup_kernel<<<1, 256>>>(w, r, p);

    // 2) D2D async copy into __constant__ (graph-capturable memcpy node)
    void* gsym = nullptr;
    cudaGetSymbolAddress(&gsym, g_cb);
    cudaMemcpyToSymbolAsync(c_cb, gsym, sizeof(CB), 0, cudaMemcpyDeviceToDevice, 0);

    // 3) main kernel
    dim3 grid(4, 64, 16);   // 4 col-tiles x 64 row-tiles x 16 batch
    dim3 block(64, 4);
    ca_kernel<<<grid, block>>>(x, (float*)d_out);
}